// round 3
// baseline (speedup 1.0000x reference)
#include <cuda_runtime.h>
#include <cuda_bf16.h>

#define NPTS     8192
#define THREADS  256
#define R        8
#define ITILE    (THREADS * R)         // 2048
#define JTILE    32
#define ITILES   (NPTS / ITILE)        // 4
#define JTILES   (NPTS / JTILE)        // 256
#define NTASKS   (3 * ITILES * JTILES) // 3072
#define GRID     592
#define TF       1024                  // fused prep threads
#define LOG2E_F  1.4426950408889634f

__device__ __forceinline__ float ex2_approx(float x) {
    float r;
    asm("ex2.approx.ftz.f32 %0, %1;" : "=f"(r) : "f"(x));
    return r;
}

// Scratch (no allocations allowed)
__device__ float4 g_bi[NPTS];   // base:   (x, y, a, 0)   i-side
__device__ float4 g_bj[NPTS];   // base:   (u, v, a, 0)   j-side  (u=-2c2*x, ...)
__device__ float4 g_ti[NPTS];   // target i-side
__device__ float4 g_tj[NPTS];   // target j-side
__device__ double g_sum[3];     // Sbb, Stt, Sbt (unnormalized)
__device__ unsigned int g_task; // dynamic task counter
__device__ unsigned int g_done; // CTA completion counter

// ---------------------------------------------------------------------------
// Fused kernel: scales/sigma, weighted means, center+scale, precompute
// (x,y,a) i-side and (u,v,a) j-side; reset counters. ONE CTA, 1024 threads.
// ---------------------------------------------------------------------------
__global__ __launch_bounds__(TF) void k_prep(const float* __restrict__ base,
                                             const float* __restrict__ tgt,
                                             const float* __restrict__ log_sigma,
                                             const float* __restrict__ log_scale) {
    const int tid = threadIdx.x;
    const float s0 = expf(log_scale[0]);
    const float s1 = expf(log_scale[1]);

    const float2* __restrict__ b2 = (const float2*)base;
    const float2* __restrict__ t2 = (const float2*)tgt;

    // ---- means (4 concurrent tree reductions in shared) ----
    double sbx = 0.0, sby = 0.0, stx = 0.0, sty = 0.0;
#pragma unroll
    for (int k = 0; k < NPTS / TF; k++) {
        int i = tid + k * TF;
        float2 pb = b2[i];
        float2 pt = t2[i];
        sbx += (double)(pb.x * s0);
        sby += (double)(pb.y * s1);
        stx += (double)(pt.x * s0);
        sty += (double)(pt.y * s1);
    }

    __shared__ double sd0[TF], sd1[TF], sd2[TF], sd3[TF];
    sd0[tid] = sbx; sd1[tid] = sby; sd2[tid] = stx; sd3[tid] = sty;
    __syncthreads();
    for (int s = TF / 2; s > 0; s >>= 1) {
        if (tid < s) {
            sd0[tid] += sd0[tid + s];
            sd1[tid] += sd1[tid + s];
            sd2[tid] += sd2[tid + s];
            sd3[tid] += sd3[tid + s];
        }
        __syncthreads();
    }

    __shared__ float sp[8];  // mbx, mby, mtx, mty, c2, m
    if (tid == 0) {
        sp[0] = (float)(sd0[0] / (double)NPTS);
        sp[1] = (float)(sd1[0] / (double)NPTS);
        sp[2] = (float)(sd2[0] / (double)NPTS);
        sp[3] = (float)(sd3[0] / (double)NPTS);
        float sigma  = expf(log_sigma[0]);
        float inv2s2 = 1.0f / (2.0f * sigma * sigma);
        float c2 = -inv2s2 * LOG2E_F;   // exp(-d2*inv2s2) = exp2(c2*d2)
        sp[4] = c2;
        sp[5] = -2.0f * c2;
        g_sum[0] = 0.0; g_sum[1] = 0.0; g_sum[2] = 0.0;
        g_task = 0u;
        g_done = 0u;
    }
    __syncthreads();

    const float mbx = sp[0], mby = sp[1], mtx = sp[2], mty = sp[3];
    const float c2 = sp[4], m = sp[5];

    // ---- prep: center, scale, precompute ----
#pragma unroll
    for (int k = 0; k < NPTS / TF; k++) {
        int i = tid + k * TF;
        float2 pb = b2[i];
        float x = pb.x * s0 - mbx;
        float y = pb.y * s1 - mby;
        float a = c2 * fmaf(x, x, y * y);
        g_bi[i] = make_float4(x, y, a, 0.0f);
        g_bj[i] = make_float4(m * x, m * y, a, 0.0f);

        float2 pt = t2[i];
        float tx = pt.x * s0 - mtx;
        float ty = pt.y * s1 - mty;
        float ta = c2 * fmaf(tx, tx, ty * ty);
        g_ti[i] = make_float4(tx, ty, ta, 0.0f);
        g_tj[i] = make_float4(m * tx, m * ty, ta, 0.0f);
    }
}

// ---------------------------------------------------------------------------
// Main kernel: 201M pair exponentials, dynamic task queue.
//   task -> (type, i-tile, j-tile); type: 0=bb, 1=tt, 2=bt
//   arg = a_i + a_j + x_i*u_j + y_i*v_j = c2 * |p_i - p_j|^2
// Last CTA finalizes: out = (Sbb + Stt - 2*Sbt) / N^2.
// ---------------------------------------------------------------------------
__device__ __forceinline__ void block_reduce_add(double v, double* dst,
                                                 double* sred, int tid) {
    sred[tid] = v;
    __syncthreads();
    for (int s = THREADS / 2; s > 0; s >>= 1) {
        if (tid < s) sred[tid] += sred[tid + s];
        __syncthreads();
    }
    if (tid == 0) atomicAdd(dst, sred[0]);
    __syncthreads();
}

__global__ __launch_bounds__(THREADS) void k_main(float* __restrict__ out) {
    __shared__ float4 tile[JTILE];
    __shared__ double sred[THREADS];
    __shared__ unsigned int s_task;

    const int tid = threadIdx.x;
    double abb = 0.0, att = 0.0, abt = 0.0;

    while (true) {
        if (tid == 0) s_task = atomicAdd(&g_task, 1u);
        __syncthreads();                 // publish s_task; old tile readers done
        unsigned int t = s_task;
        if (t >= NTASKS) break;

        int type = (int)(t % 3u);
        int rem  = (int)(t / 3u);
        int it   = rem % ITILES;
        int jt   = rem / ITILES;

        const float4* Ai = (type == 1) ? g_ti : g_bi;  // bb,bt: base;  tt: target
        const float4* Bj = (type == 0) ? g_bj : g_tj;  // bb: base;  tt,bt: target

        float xi[R], yi[R], ai[R];
        int i0 = it * ITILE + tid;
#pragma unroll
        for (int r = 0; r < R; r++) {
            float4 p = Ai[i0 + r * THREADS];
            xi[r] = p.x; yi[r] = p.y; ai[r] = p.z;
        }

        if (tid < JTILE) tile[tid] = Bj[jt * JTILE + tid];
        __syncthreads();

        float acc[R];
#pragma unroll
        for (int r = 0; r < R; r++) acc[r] = 0.0f;

#pragma unroll 2
        for (int j = 0; j < JTILE; j++) {
            float4 q = tile[j];
#pragma unroll
            for (int r = 0; r < R; r++) {
                float arg = ai[r] + q.z;
                arg = fmaf(yi[r], q.y, arg);
                arg = fmaf(xi[r], q.x, arg);
                acc[r] += ex2_approx(arg);
            }
        }

        float s = ((acc[0] + acc[1]) + (acc[2] + acc[3])) +
                  ((acc[4] + acc[5]) + (acc[6] + acc[7]));
        if      (type == 0) abb += (double)s;
        else if (type == 1) att += (double)s;
        else                abt += (double)s;
    }

    block_reduce_add(abb, &g_sum[0], sred, tid);
    block_reduce_add(att, &g_sum[1], sred, tid);
    block_reduce_add(abt, &g_sum[2], sred, tid);

    if (tid == 0) {
        __threadfence();
        unsigned int d = atomicAdd(&g_done, 1u);
        if (d == (unsigned int)(gridDim.x - 1)) {
            // coherent reads of the L2-resident accumulators
            double sbb = atomicAdd(&g_sum[0], 0.0);
            double stt = atomicAdd(&g_sum[1], 0.0);
            double sbt = atomicAdd(&g_sum[2], 0.0);
            double inv = 1.0 / ((double)NPTS * (double)NPTS);
            out[0] = (float)((sbb + stt - 2.0 * sbt) * inv);
        }
    }
}

// ---------------------------------------------------------------------------
extern "C" void kernel_launch(void* const* d_in, const int* in_sizes, int n_in,
                              void* d_out, int out_size) {
    const float* base = (const float*)d_in[0];
    const float* tgt  = (const float*)d_in[1];
    const float* lsig = (const float*)d_in[2];
    const float* lsc  = (const float*)d_in[3];

    k_prep<<<1, TF>>>(base, tgt, lsig, lsc);
    k_main<<<GRID, THREADS>>>((float*)d_out);
}

// round 5
// speedup vs baseline: 1.3147x; 1.3147x over previous
#include <cuda_runtime.h>
#include <cuda_bf16.h>

#define NPTS      8192
#define THREADS   256
#define R         8
#define ITILE     (THREADS * R)         // 2048
#define JTILE     32
#define ITILES    (NPTS / ITILE)        // 4
#define JTILES    (NPTS / JTILE)        // 256
#define NTASKS    (3 * ITILES * JTILES) // 3072
#define GRID      592                   // 4 CTAs/SM * 148 SMs -> all resident
#define PREP_CTAS 32                    // 32*256 = 8192 threads: one point idx each
#define LOG2E_F   1.4426950408889634f

__device__ __forceinline__ float ex2_approx(float x) {
    float r;
    asm("ex2.approx.ftz.f32 %0, %1;" : "=f"(r) : "f"(x));
    return r;
}
__device__ __forceinline__ unsigned int ld_acq(unsigned int* p) {
    unsigned int v;
    asm volatile("ld.acquire.gpu.u32 %0, [%1];" : "=r"(v) : "l"(p));
    return v;
}
__device__ __forceinline__ void arrive_rel(unsigned int* p) {
    asm volatile("red.release.gpu.global.add.u32 [%0], 1;" :: "l"(p) : "memory");
}

// Scratch (no allocations allowed)
__device__ float4 g_bi[NPTS];   // base:   (x, y, a, .)  i-side
__device__ float4 g_bj[NPTS];   // base:   (u, v, a, .)  j-side (u=-2c2*x, v=-2c2*y)
__device__ float4 g_ti[NPTS];   // target i-side
__device__ float4 g_tj[NPTS];   // target j-side
__device__ double g_mean[4];    // sum(bx), sum(by), sum(tx), sum(ty)  (scaled)
__device__ double g_sum[3];     // Sbb, Stt, Sbt (unnormalized)
__device__ unsigned int g_bar1; // prep-phase barrier (target PREP_CTAS)
__device__ unsigned int g_bar2; // prep-done barrier  (target PREP_CTAS)
__device__ unsigned int g_task; // dynamic task counter
__device__ unsigned int g_done; // CTA completion counter

__device__ __forceinline__ void block_reduce_add(double v, double* dst,
                                                 double* sred, int tid) {
    sred[tid] = v;
    __syncthreads();
    for (int s = THREADS / 2; s > 0; s >>= 1) {
        if (tid < s) sred[tid] += sred[tid + s];
        __syncthreads();
    }
    if (tid == 0) atomicAdd(dst, sred[0]);
    __syncthreads();
}

// ---------------------------------------------------------------------------
// Single fused kernel:
//   Phase A (32 CTAs): scaled coordinate sums -> g_mean (double atomics)
//   Phase B (32 CTAs): center + scale + precompute (x,y,a)/(u,v,a)
//   Phase C (all 592): 201M pair exponentials via dynamic task queue
//     arg = a_i + a_j + x_i*u_j + y_i*v_j = c2 * |p_i - p_j|^2,  k = exp2(arg)
//   Last CTA: combine terms, write out, reset state for next graph replay.
// ---------------------------------------------------------------------------
__global__ __launch_bounds__(THREADS, 4) void k_fused(
        const float* __restrict__ base, const float* __restrict__ tgt,
        const float* __restrict__ log_sigma, const float* __restrict__ log_scale,
        float* __restrict__ out) {
    __shared__ float4 tile[JTILE];
    __shared__ double sred[THREADS];
    __shared__ float  sp[4];
    __shared__ unsigned int s_task;

    const int tid = threadIdx.x;
    const int cta = blockIdx.x;

    // Every thread can cheaply derive the scalar params from the tiny inputs.
    const float s0 = expf(log_scale[0]);
    const float s1 = expf(log_scale[1]);
    const float sigma = expf(log_sigma[0]);
    const float c2 = -(1.0f / (2.0f * sigma * sigma)) * LOG2E_F;
    const float m  = -2.0f * c2;

    if (cta < PREP_CTAS) {
        // ---- Phase A: weighted sums of scaled coordinates ----
        const float2* __restrict__ b2 = (const float2*)base;
        const float2* __restrict__ t2 = (const float2*)tgt;
        const int i = cta * THREADS + tid;          // 0..8191
        const float2 pb = b2[i];
        const float2 pt = t2[i];
        const float bx = pb.x * s0, by = pb.y * s1;
        const float tx = pt.x * s0, ty = pt.y * s1;

        block_reduce_add((double)bx, &g_mean[0], sred, tid);
        block_reduce_add((double)by, &g_mean[1], sred, tid);
        block_reduce_add((double)tx, &g_mean[2], sred, tid);
        block_reduce_add((double)ty, &g_mean[3], sred, tid);

        if (tid == 0) {
            __threadfence();
            arrive_rel(&g_bar1);
            while (ld_acq(&g_bar1) < PREP_CTAS) { }
        }
        __syncthreads();

        // ---- Phase B: center, scale, precompute ----
        if (tid < 4) sp[tid] = (float)(atomicAdd(&g_mean[tid], 0.0) / (double)NPTS);
        __syncthreads();
        const float mbx = sp[0], mby = sp[1], mtx = sp[2], mty = sp[3];

        {
            float x = bx - mbx;
            float y = by - mby;
            float a = c2 * fmaf(x, x, y * y);
            g_bi[i] = make_float4(x, y, a, 0.0f);
            g_bj[i] = make_float4(m * x, m * y, a, 0.0f);

            float xt = tx - mtx;
            float yt = ty - mty;
            float at = c2 * fmaf(xt, xt, yt * yt);
            g_ti[i] = make_float4(xt, yt, at, 0.0f);
            g_tj[i] = make_float4(m * xt, m * yt, at, 0.0f);
        }
        __threadfence();
        __syncthreads();
        if (tid == 0) arrive_rel(&g_bar2);
    }

    // ---- All CTAs wait until prep data is published ----
    if (tid == 0) {
        while (ld_acq(&g_bar2) < PREP_CTAS) { }
    }
    __syncthreads();

    // ---- Phase C: pair loop ----
    double abb = 0.0, att = 0.0, abt = 0.0;

    while (true) {
        if (tid == 0) s_task = atomicAdd(&g_task, 1u);
        __syncthreads();                 // publish s_task; old tile readers done
        unsigned int t = s_task;
        if (t >= NTASKS) break;

        int type = (int)(t % 3u);
        int rem  = (int)(t / 3u);
        int it   = rem % ITILES;
        int jt   = rem / ITILES;

        const float4* Ai = (type == 1) ? g_ti : g_bi;  // bb,bt: base;  tt: target
        const float4* Bj = (type == 0) ? g_bj : g_tj;  // bb: base;  tt,bt: target

        float xi[R], yi[R], ai[R];
        int i0 = it * ITILE + tid;
#pragma unroll
        for (int r = 0; r < R; r++) {
            float4 p = Ai[i0 + r * THREADS];
            xi[r] = p.x; yi[r] = p.y; ai[r] = p.z;
        }

        if (tid < JTILE) tile[tid] = Bj[jt * JTILE + tid];
        __syncthreads();

        float acc[R];
#pragma unroll
        for (int r = 0; r < R; r++) acc[r] = 0.0f;

#pragma unroll 2
        for (int j = 0; j < JTILE; j++) {
            float4 q = tile[j];
#pragma unroll
            for (int r = 0; r < R; r++) {
                float arg = ai[r] + q.z;
                arg = fmaf(yi[r], q.y, arg);
                arg = fmaf(xi[r], q.x, arg);
                acc[r] += ex2_approx(arg);
            }
        }

        float s = ((acc[0] + acc[1]) + (acc[2] + acc[3])) +
                  ((acc[4] + acc[5]) + (acc[6] + acc[7]));
        if      (type == 0) abb += (double)s;
        else if (type == 1) att += (double)s;
        else                abt += (double)s;
    }

    block_reduce_add(abb, &g_sum[0], sred, tid);
    block_reduce_add(att, &g_sum[1], sred, tid);
    block_reduce_add(abt, &g_sum[2], sred, tid);

    // ---- Finalize + state reset (last CTA) ----
    if (tid == 0) {
        __threadfence();
        unsigned int d = atomicAdd(&g_done, 1u);
        if (d == (unsigned int)(GRID - 1)) {
            double sbb = atomicAdd(&g_sum[0], 0.0);
            double stt = atomicAdd(&g_sum[1], 0.0);
            double sbt = atomicAdd(&g_sum[2], 0.0);
            double inv = 1.0 / ((double)NPTS * (double)NPTS);
            out[0] = (float)((sbb + stt - 2.0 * sbt) * inv);
            // reset for next graph replay
            g_sum[0] = 0.0; g_sum[1] = 0.0; g_sum[2] = 0.0;
            g_mean[0] = 0.0; g_mean[1] = 0.0; g_mean[2] = 0.0; g_mean[3] = 0.0;
            g_task = 0u; g_bar1 = 0u; g_bar2 = 0u; g_done = 0u;
            __threadfence();
        }
    }
}

// ---------------------------------------------------------------------------
extern "C" void kernel_launch(void* const* d_in, const int* in_sizes, int n_in,
                              void* d_out, int out_size) {
    const float* base = (const float*)d_in[0];
    const float* tgt  = (const float*)d_in[1];
    const float* lsig = (const float*)d_in[2];
    const float* lsc  = (const float*)d_in[3];

    k_fused<<<GRID, THREADS>>>(base, tgt, lsig, lsc, (float*)d_out);
}

// round 6
// speedup vs baseline: 1.4473x; 1.1009x over previous
#include <cuda_runtime.h>
#include <cuda_bf16.h>

#define NPTS      8192
#define THREADS   256
#define R         8
#define ITILE     (THREADS * R)         // 2048
#define JTILE     32
#define ITILES    (NPTS / ITILE)        // 4
#define JTILES    (NPTS / JTILE)        // 256
#define TASKS_PER_TYPE (ITILES * JTILES)   // 1024
#define NTASKS    (3 * TASKS_PER_TYPE)     // 3072: bb [0,1024) tt [1024,2048) bt [2048,3072)
#define GRID      592                   // 4 CTAs/SM * 148 SMs -> all resident
#define PREP_CTAS 32                    // 32*256 = 8192 threads: one point idx each
#define LOG2E_F   1.4426950408889634f

__device__ __forceinline__ float ex2_approx(float x) {
    float r;
    asm("ex2.approx.ftz.f32 %0, %1;" : "=f"(r) : "f"(x));
    return r;
}
__device__ __forceinline__ unsigned int ld_acq(unsigned int* p) {
    unsigned int v;
    asm volatile("ld.acquire.gpu.u32 %0, [%1];" : "=r"(v) : "l"(p));
    return v;
}
__device__ __forceinline__ void st_rel(unsigned int* p, unsigned int v) {
    asm volatile("st.release.gpu.global.u32 [%0], %1;" :: "l"(p), "r"(v) : "memory");
}

// Scratch (no allocations allowed)
__device__ double g_mean[2];    // sum((bx-tx)*s0), sum((by-ty)*s1)
__device__ float  g_delta[2];   // delta = centroid(base) - centroid(target), scaled
__device__ double g_sum[3];     // Sbb, Stt, Sbt (unnormalized)
__device__ unsigned int g_bar1; // prep reduction completion counter
__device__ unsigned int g_flag; // delta-ready flag
__device__ unsigned int g_task; // dynamic task counter
__device__ unsigned int g_done; // CTA completion counter

__device__ __forceinline__ void block_reduce_add(double v, double* dst,
                                                 double* sred, int tid) {
    sred[tid] = v;
    __syncthreads();
    for (int s = THREADS / 2; s > 0; s >>= 1) {
        if (tid < s) sred[tid] += sred[tid + s];
        __syncthreads();
    }
    if (tid == 0) atomicAdd(dst, sred[0]);
    __syncthreads();
}

// ---------------------------------------------------------------------------
// Single fused kernel, barrier-free main path.
//
// Centering is algebraically folded away:
//   bb: (bi-cb)-(bj-cb) = bi-bj          -> no prep needed
//   tt: (ti-ct)-(tj-ct) = ti-tj          -> no prep needed
//   bt: (bi-cb)-(tj-ct) = bi-(tj+delta)  -> needs only delta = cb-ct
//
// Tasks ordered bb, tt, bt. CTAs 0..31 compute delta (2 block reductions +
// atomics) concurrently with early bb tasks; by the time bt tasks (last
// third) are issued, delta has long been published. All operands are
// computed on the fly from raw inputs (L2-resident), no staging arrays.
//   arg = a_i + a_j' + x_i*u_j' + y_i*v_j' = c2*|p_i - p_j'|^2, k = exp2(arg)
// ---------------------------------------------------------------------------
__global__ __launch_bounds__(THREADS, 4) void k_fused(
        const float* __restrict__ base, const float* __restrict__ tgt,
        const float* __restrict__ log_sigma, const float* __restrict__ log_scale,
        float* __restrict__ out) {
    __shared__ float4 tile[JTILE];
    __shared__ double sred[THREADS];
    __shared__ unsigned int s_task;
    __shared__ float s_dx, s_dy;
    __shared__ int s_have;

    const int tid = threadIdx.x;
    const int cta = blockIdx.x;

    if (tid == 0) { s_have = 0; s_dx = 0.0f; s_dy = 0.0f; }

    // Scalar params derived by every thread from the tiny inputs.
    const float s0 = expf(log_scale[0]);
    const float s1 = expf(log_scale[1]);
    const float sigma = expf(log_sigma[0]);
    const float c2 = -(1.0f / (2.0f * sigma * sigma)) * LOG2E_F;
    const float m  = -2.0f * c2;

    const float2* __restrict__ b2 = (const float2*)base;
    const float2* __restrict__ t2 = (const float2*)tgt;

    // ---- delta reduction (32 CTAs, overlapped with bb tasks elsewhere) ----
    if (cta < PREP_CTAS) {
        const int i = cta * THREADS + tid;          // 0..8191
        const float2 pb = b2[i];
        const float2 pt = t2[i];
        block_reduce_add((double)(pb.x * s0) - (double)(pt.x * s0),
                         &g_mean[0], sred, tid);
        block_reduce_add((double)(pb.y * s1) - (double)(pt.y * s1),
                         &g_mean[1], sred, tid);
        if (tid == 0) {
            __threadfence();
            unsigned int d = atomicAdd(&g_bar1, 1u);
            if (d == PREP_CTAS - 1) {
                g_delta[0] = (float)(atomicAdd(&g_mean[0], 0.0) / (double)NPTS);
                g_delta[1] = (float)(atomicAdd(&g_mean[1], 0.0) / (double)NPTS);
                st_rel(&g_flag, 1u);
            }
        }
    }

    // ---- pair-task loop (all CTAs, starts immediately) ----
    double abb = 0.0, att = 0.0, abt = 0.0;

    while (true) {
        if (tid == 0) s_task = atomicAdd(&g_task, 1u);
        __syncthreads();                 // publish s_task; old tile readers done
        unsigned int t = s_task;
        if (t >= NTASKS) break;

        int type = (int)(t / TASKS_PER_TYPE);       // 0 bb, 1 tt, 2 bt
        int rem  = (int)(t % TASKS_PER_TYPE);
        int it   = rem % ITILES;
        int jt   = rem / ITILES;

        // bt gate: one-time per CTA; delta long published by now.
        if (type == 2 && s_have == 0) {
            if (tid == 0) {
                while (ld_acq(&g_flag) == 0u) { }
                s_dx = g_delta[0];
                s_dy = g_delta[1];
                s_have = 1;
            }
            __syncthreads();
        }

        const float2* __restrict__ Araw = (type == 1) ? t2 : b2; // i-side
        const float2* __restrict__ Braw = (type == 0) ? b2 : t2; // j-side
        const float dx = (type == 2) ? s_dx : 0.0f;
        const float dy = (type == 2) ? s_dy : 0.0f;

        // i-side on the fly: x, y, a = c2*|p|^2
        float xi[R], yi[R], ai[R];
        int i0 = it * ITILE + tid;
#pragma unroll
        for (int r = 0; r < R; r++) {
            float2 p = Araw[i0 + r * THREADS];
            float x = p.x * s0;
            float y = p.y * s1;
            xi[r] = x; yi[r] = y;
            ai[r] = c2 * fmaf(x, x, y * y);
        }

        // j-side tile on the fly: (u, v, a) with optional delta shift
        if (tid < JTILE) {
            float2 q = Braw[jt * JTILE + tid];
            float x = fmaf(q.x, s0, dx);
            float y = fmaf(q.y, s1, dy);
            float a = c2 * fmaf(x, x, y * y);
            tile[tid] = make_float4(m * x, m * y, a, 0.0f);
        }
        __syncthreads();

        float acc[R];
#pragma unroll
        for (int r = 0; r < R; r++) acc[r] = 0.0f;

#pragma unroll 2
        for (int j = 0; j < JTILE; j++) {
            float4 q = tile[j];
#pragma unroll
            for (int r = 0; r < R; r++) {
                float arg = ai[r] + q.z;
                arg = fmaf(yi[r], q.y, arg);
                arg = fmaf(xi[r], q.x, arg);
                acc[r] += ex2_approx(arg);
            }
        }

        float s = ((acc[0] + acc[1]) + (acc[2] + acc[3])) +
                  ((acc[4] + acc[5]) + (acc[6] + acc[7]));
        if      (type == 0) abb += (double)s;
        else if (type == 1) att += (double)s;
        else                abt += (double)s;
    }

    block_reduce_add(abb, &g_sum[0], sred, tid);
    block_reduce_add(att, &g_sum[1], sred, tid);
    block_reduce_add(abt, &g_sum[2], sred, tid);

    // ---- finalize + state reset (last CTA) ----
    if (tid == 0) {
        __threadfence();
        unsigned int d = atomicAdd(&g_done, 1u);
        if (d == (unsigned int)(GRID - 1)) {
            double sbb = atomicAdd(&g_sum[0], 0.0);
            double stt = atomicAdd(&g_sum[1], 0.0);
            double sbt = atomicAdd(&g_sum[2], 0.0);
            double inv = 1.0 / ((double)NPTS * (double)NPTS);
            out[0] = (float)((sbb + stt - 2.0 * sbt) * inv);
            // reset for next graph replay
            g_sum[0] = 0.0; g_sum[1] = 0.0; g_sum[2] = 0.0;
            g_mean[0] = 0.0; g_mean[1] = 0.0;
            g_task = 0u; g_bar1 = 0u; g_flag = 0u; g_done = 0u;
            __threadfence();
        }
    }
}

// ---------------------------------------------------------------------------
extern "C" void kernel_launch(void* const* d_in, const int* in_sizes, int n_in,
                              void* d_out, int out_size) {
    const float* base = (const float*)d_in[0];
    const float* tgt  = (const float*)d_in[1];
    const float* lsig = (const float*)d_in[2];
    const float* lsc  = (const float*)d_in[3];

    k_fused<<<GRID, THREADS>>>(base, tgt, lsig, lsc, (float*)d_out);
}

// round 7
// speedup vs baseline: 1.6796x; 1.1605x over previous
#include <cuda_runtime.h>
#include <cuda_bf16.h>

#define NPTS      8192
#define THREADS   256
#define R         4
#define ITILE     (THREADS * R)         // 1024
#define JTILE     16
#define ITILES    (NPTS / ITILE)        // 8
#define JTILES    (NPTS / JTILE)        // 512
#define JB        (ITILE / JTILE)       // 64 j-blocks per i-block
// symmetric types: for i-block k, valid j-blocks = JTILES - k*JB
#define TPT_SYM   2304                  // sum_{k=0..7}(512-64k)
#define TPT_FULL  (ITILES * JTILES)     // 4096
#define NTASKS    (2 * TPT_SYM + TPT_FULL)  // 8704: bb, tt, bt(last)
#define GRID      592                   // 4 CTAs/SM * 148 SMs
#define PREP_CTAS 32
#define LOG2E_F   1.4426950408889634f

__device__ __forceinline__ float ex2_approx(float x) {
    float r;
    asm("ex2.approx.ftz.f32 %0, %1;" : "=f"(r) : "f"(x));
    return r;
}
__device__ __forceinline__ unsigned int ld_acq(unsigned int* p) {
    unsigned int v;
    asm volatile("ld.acquire.gpu.u32 %0, [%1];" : "=r"(v) : "l"(p));
    return v;
}
__device__ __forceinline__ void st_rel(unsigned int* p, unsigned int v) {
    asm volatile("st.release.gpu.global.u32 [%0], %1;" :: "l"(p), "r"(v) : "memory");
}

// Scratch (no allocations allowed)
__device__ double g_mean[2];    // sum((bx-tx)*s0), sum((by-ty)*s1)
__device__ float  g_delta[2];   // centroid(base) - centroid(target), scaled
__device__ double g_sum[3];     // Sbb, Stt, Sbt (unnormalized)
__device__ unsigned int g_bar1; // prep reduction completion counter
__device__ unsigned int g_flag; // delta-ready flag
__device__ unsigned int g_task; // dynamic task counter
__device__ unsigned int g_done; // CTA completion counter

__device__ __forceinline__ void block_reduce_add(double v, double* dst,
                                                 double* sred, int tid) {
    sred[tid] = v;
    __syncthreads();
    for (int s = THREADS / 2; s > 0; s >>= 1) {
        if (tid < s) sred[tid] += sred[tid + s];
        __syncthreads();
    }
    if (tid == 0) atomicAdd(dst, sred[0]);
    __syncthreads();
}

// ---------------------------------------------------------------------------
// Single fused kernel, symmetry-pruned pair space.
//
//   bb/tt are symmetric: skip j-blocks strictly below the i-block,
//   weight j-blocks strictly above it x2, diagonal-straddling blocks x1.
//   Effective exp count: 2.125*N^2 instead of 3*N^2.
//
//   Centering folded away (shift invariance); only bt needs
//   delta = cb - ct, reduced by CTAs 0..31 concurrently with bb tasks
//   (bt tasks are last in the queue).
//   arg = a_i + a_j + x_i*u_j + y_i*v_j = c2*|p_i - p_j|^2, k = exp2(arg)
// ---------------------------------------------------------------------------
__global__ __launch_bounds__(THREADS, 4) void k_fused(
        const float* __restrict__ base, const float* __restrict__ tgt,
        const float* __restrict__ log_sigma, const float* __restrict__ log_scale,
        float* __restrict__ out) {
    __shared__ float4 tile[JTILE];
    __shared__ double sred[THREADS];
    __shared__ unsigned int s_task;
    __shared__ float s_dx, s_dy;
    __shared__ int s_have;

    const int tid = threadIdx.x;
    const int cta = blockIdx.x;

    if (tid == 0) { s_have = 0; s_dx = 0.0f; s_dy = 0.0f; }

    const float s0 = expf(log_scale[0]);
    const float s1 = expf(log_scale[1]);
    const float sigma = expf(log_sigma[0]);
    const float c2 = -(1.0f / (2.0f * sigma * sigma)) * LOG2E_F;
    const float m  = -2.0f * c2;

    const float2* __restrict__ b2 = (const float2*)base;
    const float2* __restrict__ t2 = (const float2*)tgt;

    // ---- delta reduction (32 CTAs, overlapped with bb tasks elsewhere) ----
    if (cta < PREP_CTAS) {
        const int i = cta * THREADS + tid;          // 0..8191
        const float2 pb = b2[i];
        const float2 pt = t2[i];
        block_reduce_add((double)(pb.x * s0) - (double)(pt.x * s0),
                         &g_mean[0], sred, tid);
        block_reduce_add((double)(pb.y * s1) - (double)(pt.y * s1),
                         &g_mean[1], sred, tid);
        if (tid == 0) {
            __threadfence();
            unsigned int d = atomicAdd(&g_bar1, 1u);
            if (d == PREP_CTAS - 1) {
                g_delta[0] = (float)(atomicAdd(&g_mean[0], 0.0) / (double)NPTS);
                g_delta[1] = (float)(atomicAdd(&g_mean[1], 0.0) / (double)NPTS);
                st_rel(&g_flag, 1u);
            }
        }
    }

    // ---- pair-task loop ----
    double abb = 0.0, att = 0.0, abt = 0.0;

    while (true) {
        if (tid == 0) s_task = atomicAdd(&g_task, 1u);
        __syncthreads();                 // publish s_task; old tile readers done
        unsigned int t = s_task;
        if (t >= NTASKS) break;

        // decode task -> (type, it, jt, weight)
        int type, it, jt;
        float w = 1.0f;
        if (t < 2u * TPT_SYM) {
            type = (t < TPT_SYM) ? 0 : 1;
            int rem = (int)(t % TPT_SYM);
            it = 0;
            int rowcnt = JTILES;                 // 512 - 64*it
#pragma unroll 1
            while (rem >= rowcnt) { rem -= rowcnt; it++; rowcnt -= JB; }
            jt = it * JB + rem;                  // jt >= it*JB always
            if (jt >= (it + 1) * JB) w = 2.0f;   // strictly-upper block
        } else {
            type = 2;
            int rem = (int)(t - 2u * TPT_SYM);
            it = rem % ITILES;
            jt = rem / ITILES;
        }

        // bt gate: one-time per CTA; delta long published by now.
        if (type == 2 && s_have == 0) {
            if (tid == 0) {
                while (ld_acq(&g_flag) == 0u) { }
                s_dx = g_delta[0];
                s_dy = g_delta[1];
                s_have = 1;
            }
            __syncthreads();
        }

        const float2* __restrict__ Araw = (type == 1) ? t2 : b2; // i-side
        const float2* __restrict__ Braw = (type == 0) ? b2 : t2; // j-side
        const float dx = (type == 2) ? s_dx : 0.0f;
        const float dy = (type == 2) ? s_dy : 0.0f;

        // i-side on the fly: x, y, a = c2*|p|^2
        float xi[R], yi[R], ai[R];
        int i0 = it * ITILE + tid;
#pragma unroll
        for (int r = 0; r < R; r++) {
            float2 p = Araw[i0 + r * THREADS];
            float x = p.x * s0;
            float y = p.y * s1;
            xi[r] = x; yi[r] = y;
            ai[r] = c2 * fmaf(x, x, y * y);
        }

        // j-side tile on the fly: (u, v, a) with optional delta shift
        if (tid < JTILE) {
            float2 q = Braw[jt * JTILE + tid];
            float x = fmaf(q.x, s0, dx);
            float y = fmaf(q.y, s1, dy);
            float a = c2 * fmaf(x, x, y * y);
            tile[tid] = make_float4(m * x, m * y, a, 0.0f);
        }
        __syncthreads();

        float acc[R];
#pragma unroll
        for (int r = 0; r < R; r++) acc[r] = 0.0f;

#pragma unroll 4
        for (int j = 0; j < JTILE; j++) {
            float4 q = tile[j];
#pragma unroll
            for (int r = 0; r < R; r++) {
                float arg = ai[r] + q.z;
                arg = fmaf(yi[r], q.y, arg);
                arg = fmaf(xi[r], q.x, arg);
                acc[r] += ex2_approx(arg);
            }
        }

        float s = (acc[0] + acc[1]) + (acc[2] + acc[3]);
        double ws = (double)w * (double)s;
        if      (type == 0) abb += ws;
        else if (type == 1) att += ws;
        else                abt += ws;
    }

    block_reduce_add(abb, &g_sum[0], sred, tid);
    block_reduce_add(att, &g_sum[1], sred, tid);
    block_reduce_add(abt, &g_sum[2], sred, tid);

    // ---- finalize + state reset (last CTA) ----
    if (tid == 0) {
        __threadfence();
        unsigned int d = atomicAdd(&g_done, 1u);
        if (d == (unsigned int)(GRID - 1)) {
            double sbb = atomicAdd(&g_sum[0], 0.0);
            double stt = atomicAdd(&g_sum[1], 0.0);
            double sbt = atomicAdd(&g_sum[2], 0.0);
            double inv = 1.0 / ((double)NPTS * (double)NPTS);
            out[0] = (float)((sbb + stt - 2.0 * sbt) * inv);
            // reset for next graph replay
            g_sum[0] = 0.0; g_sum[1] = 0.0; g_sum[2] = 0.0;
            g_mean[0] = 0.0; g_mean[1] = 0.0;
            g_task = 0u; g_bar1 = 0u; g_flag = 0u; g_done = 0u;
            __threadfence();
        }
    }
}

// ---------------------------------------------------------------------------
extern "C" void kernel_launch(void* const* d_in, const int* in_sizes, int n_in,
                              void* d_out, int out_size) {
    const float* base = (const float*)d_in[0];
    const float* tgt  = (const float*)d_in[1];
    const float* lsig = (const float*)d_in[2];
    const float* lsc  = (const float*)d_in[3];

    k_fused<<<GRID, THREADS>>>(base, tgt, lsig, lsc, (float*)d_out);
}

// round 8
// speedup vs baseline: 1.7633x; 1.0499x over previous
#include <cuda_runtime.h>
#include <cuda_bf16.h>

#define NPTS      8192
#define THREADS   256
#define WPC       8                     // warps per CTA
#define R         8                     // i-points per lane
#define ICHUNK    256                   // i-points per warp task (32*R)
#define IBLKS     (NPTS / ICHUNK)       // 32
#define JTILE     16                    // j-points per warp task
#define JBLKS     (NPTS / JTILE)        // 512
#define JGROUP    16                    // j-blocks per 256-pt j-group
#define RECT_P    (IBLKS / 2)           // 16
#define RECT_C    (IBLKS + 1)           // 33
#define TPT_SYM   (RECT_P * RECT_C * JGROUP)  // 8448
#define TPT_FULL  (IBLKS * JBLKS)             // 16384
#define NTASKS    (2 * TPT_SYM + TPT_FULL)    // 33280: bb, tt, bt(last)
#define GRID      592                   // 4 CTAs/SM * 148 SMs, all resident
#define PREP_CTAS 32
#define LOG2E_F   1.4426950408889634f
#define FULLMASK  0xFFFFFFFFu

__device__ __forceinline__ float ex2_approx(float x) {
    float r;
    asm("ex2.approx.ftz.f32 %0, %1;" : "=f"(r) : "f"(x));
    return r;
}
__device__ __forceinline__ unsigned int ld_acq(unsigned int* p) {
    unsigned int v;
    asm volatile("ld.acquire.gpu.u32 %0, [%1];" : "=r"(v) : "l"(p));
    return v;
}
__device__ __forceinline__ void st_rel(unsigned int* p, unsigned int v) {
    asm volatile("st.release.gpu.global.u32 [%0], %1;" :: "l"(p), "r"(v) : "memory");
}

// Scratch (no allocations allowed)
__device__ double g_mean[2];    // sum((bx-tx)*s0), sum((by-ty)*s1)
__device__ float  g_delta[2];   // centroid(base) - centroid(target), scaled
__device__ double g_sum[3];     // Sbb, Stt, Sbt (unnormalized)
__device__ unsigned int g_bar1; // prep reduction completion counter
__device__ unsigned int g_flag; // delta-ready flag
__device__ unsigned int g_task; // dynamic task counter
__device__ unsigned int g_done; // CTA completion counter

__device__ __forceinline__ void block_reduce_add(double v, double* dst,
                                                 double* sred, int tid) {
    sred[tid] = v;
    __syncthreads();
    for (int s = THREADS / 2; s > 0; s >>= 1) {
        if (tid < s) sred[tid] += sred[tid + s];
        __syncthreads();
    }
    if (tid == 0) atomicAdd(dst, sred[0]);
    __syncthreads();
}

// ---------------------------------------------------------------------------
// Warp-autonomous symmetry-pruned pair loop.
//
//  bb/tt symmetric at 256x256 block granularity: upper triangle incl.
//  diagonal; strictly-upper blocks weighted x2. The 528-group triangle is
//  remapped to a 16x33 rectangle (row p paired with row 31-p) for O(1)
//  decode. Effective exp count: 2.031*N^2.
//
//  Each warp pulls tasks (i-chunk 256, j-block 16) from a global counter;
//  atomic result consumed only after current task -> latency hidden. No
//  block barriers in the hot loop; j-tile is warp-private smem + syncwarp.
//
//  Centering folded away (shift invariance); only bt needs delta = cb-ct,
//  reduced by CTAs 0..31 before they join; bt tasks are last in the queue.
//  arg = a_i + a_j + x_i*u_j + y_i*v_j = c2*|p_i - p_j|^2,  k = exp2(arg)
// ---------------------------------------------------------------------------
__global__ __launch_bounds__(THREADS, 4) void k_fused(
        const float* __restrict__ base, const float* __restrict__ tgt,
        const float* __restrict__ log_sigma, const float* __restrict__ log_scale,
        float* __restrict__ out) {
    __shared__ float4 wtile[WPC][JTILE];
    __shared__ double sred[THREADS];

    const int tid  = threadIdx.x;
    const int wid  = tid >> 5;
    const int lane = tid & 31;
    const int cta  = blockIdx.x;

    const float s0 = expf(log_scale[0]);
    const float s1 = expf(log_scale[1]);
    const float sigma = expf(log_sigma[0]);
    const float c2 = -(1.0f / (2.0f * sigma * sigma)) * LOG2E_F;
    const float m  = -2.0f * c2;

    const float2* __restrict__ b2 = (const float2*)base;
    const float2* __restrict__ t2 = (const float2*)tgt;

    // ---- delta reduction (32 CTAs; bt tasks are last, so this hides) ----
    if (cta < PREP_CTAS) {
        const int i = cta * THREADS + tid;          // 0..8191
        const float2 pb = b2[i];
        const float2 pt = t2[i];
        block_reduce_add((double)(pb.x * s0) - (double)(pt.x * s0),
                         &g_mean[0], sred, tid);
        block_reduce_add((double)(pb.y * s1) - (double)(pt.y * s1),
                         &g_mean[1], sred, tid);
        if (tid == 0) {
            __threadfence();
            unsigned int d = atomicAdd(&g_bar1, 1u);
            if (d == PREP_CTAS - 1) {
                g_delta[0] = (float)(atomicAdd(&g_mean[0], 0.0) / (double)NPTS);
                g_delta[1] = (float)(atomicAdd(&g_mean[1], 0.0) / (double)NPTS);
                st_rel(&g_flag, 1u);
            }
        }
    }

    // ---- warp task loop ----
    double abb = 0.0, att = 0.0, abt = 0.0;
    float dx = 0.0f, dy = 0.0f;
    bool have_delta = false;

    unsigned int tnext = 0u;
    if (lane == 0) tnext = atomicAdd(&g_task, 1u);
    unsigned int t = __shfl_sync(FULLMASK, tnext, 0);

    while (t < NTASKS) {
        // prefetch next task; result consumed only after compute
        if (lane == 0) tnext = atomicAdd(&g_task, 1u);

        // ---- decode task -> (type, it, jt, w) ----
        int type, it, jt;
        float w = 1.0f;
        if (t < 2u * TPT_SYM) {
            type = (t < TPT_SYM) ? 0 : 1;
            unsigned int rem = (t < TPT_SYM) ? t : t - TPT_SYM;
            unsigned int g   = rem >> 4;            // group index [0,528)
            unsigned int sub = rem & 15u;
            unsigned int p = g / RECT_C;            // [0,16)
            unsigned int c = g % RECT_C;            // [0,33)
            unsigned int jg;
            if (c < (unsigned)(IBLKS - p)) { it = (int)p;              jg = p + c; }
            else                           { it = (int)(IBLKS - 1 - p); jg = c - 1; }
            if ((int)jg > it) w = 2.0f;             // strictly-upper block
            jt = (int)(jg * JGROUP + sub);
        } else {
            type = 2;
            unsigned int rem = t - 2u * TPT_SYM;
            it = (int)(rem & (IBLKS - 1));
            jt = (int)(rem >> 5);                   // rem / IBLKS
        }

        // bt gate: one-time per warp; delta long published by now
        if (type == 2 && !have_delta) {
            while (ld_acq(&g_flag) == 0u) { }
            dx = g_delta[0];
            dy = g_delta[1];
            have_delta = true;
        }

        const float2* __restrict__ Araw = (type == 1) ? t2 : b2; // i-side
        const float2* __restrict__ Braw = (type == 0) ? b2 : t2; // j-side
        const float jdx = (type == 2) ? dx : 0.0f;
        const float jdy = (type == 2) ? dy : 0.0f;

        // i-side on the fly: x, y, a = c2*|p|^2
        float xi[R], yi[R], ai[R];
        int i0 = it * ICHUNK + lane;
#pragma unroll
        for (int r = 0; r < R; r++) {
            float2 p = Araw[i0 + r * 32];
            float x = p.x * s0;
            float y = p.y * s1;
            xi[r] = x; yi[r] = y;
            ai[r] = c2 * fmaf(x, x, y * y);
        }

        // warp-private j-tile: (u, v, a) with optional delta shift
        __syncwarp();                                // prior tile reads done
        if (lane < JTILE) {
            float2 q = Braw[jt * JTILE + lane];
            float x = fmaf(q.x, s0, jdx);
            float y = fmaf(q.y, s1, jdy);
            float a = c2 * fmaf(x, x, y * y);
            wtile[wid][lane] = make_float4(m * x, m * y, a, 0.0f);
        }
        __syncwarp();

        float acc[R];
#pragma unroll
        for (int r = 0; r < R; r++) acc[r] = 0.0f;

#pragma unroll 4
        for (int j = 0; j < JTILE; j++) {
            float4 q = wtile[wid][j];
#pragma unroll
            for (int r = 0; r < R; r++) {
                float arg = ai[r] + q.z;
                arg = fmaf(yi[r], q.y, arg);
                arg = fmaf(xi[r], q.x, arg);
                acc[r] += ex2_approx(arg);
            }
        }

        float s = ((acc[0] + acc[1]) + (acc[2] + acc[3])) +
                  ((acc[4] + acc[5]) + (acc[6] + acc[7]));
        double ws = (double)w * (double)s;
        if      (type == 0) abb += ws;
        else if (type == 1) att += ws;
        else                abt += ws;

        t = __shfl_sync(FULLMASK, tnext, 0);
    }

    // ---- CTA-level reduction, then 3 atomics per CTA ----
    __syncthreads();
    block_reduce_add(abb, &g_sum[0], sred, tid);
    block_reduce_add(att, &g_sum[1], sred, tid);
    block_reduce_add(abt, &g_sum[2], sred, tid);

    // ---- finalize + state reset (last CTA) ----
    if (tid == 0) {
        __threadfence();
        unsigned int d = atomicAdd(&g_done, 1u);
        if (d == (unsigned int)(GRID - 1)) {
            double sbb = atomicAdd(&g_sum[0], 0.0);
            double stt = atomicAdd(&g_sum[1], 0.0);
            double sbt = atomicAdd(&g_sum[2], 0.0);
            double inv = 1.0 / ((double)NPTS * (double)NPTS);
            out[0] = (float)((sbb + stt - 2.0 * sbt) * inv);
            // reset for next graph replay
            g_sum[0] = 0.0; g_sum[1] = 0.0; g_sum[2] = 0.0;
            g_mean[0] = 0.0; g_mean[1] = 0.0;
            g_task = 0u; g_bar1 = 0u; g_flag = 0u; g_done = 0u;
            __threadfence();
        }
    }
}

// ---------------------------------------------------------------------------
extern "C" void kernel_launch(void* const* d_in, const int* in_sizes, int n_in,
                              void* d_out, int out_size) {
    const float* base = (const float*)d_in[0];
    const float* tgt  = (const float*)d_in[1];
    const float* lsig = (const float*)d_in[2];
    const float* lsc  = (const float*)d_in[3];

    k_fused<<<GRID, THREADS>>>(base, tgt, lsig, lsc, (float*)d_out);
}